// round 4
// baseline (speedup 1.0000x reference)
#include <cuda_runtime.h>
#include <cuda_bf16.h>
#include <math.h>
#include <stdint.h>

#define T_STEPS 8
#define NN      10000
#define EE      200000
#define FIN     32
#define HID     128
#define OUTD    64
#define G4      256            // 4*OUT
#define MROWS   (T_STEPS*NN)   // 80000
#define EPSBN   1e-5f

// weight-plane offsets ([n][k] bf16 layout, packed)
#define WO0 0            // wg0^T   128x32
#define WO1 4096         // wg1^T   128x128
#define WO2 20480        // wg2^T   128x128
#define WO3 36864        // w_ih0   256x128
#define WO4 69632        // w_ih1   256x64
#define WO5 86016        // w_ih2   256x64
#define WTOT 102400
#define PREP_ELEMS (WTOT + 768)

// ===================== scratch (device globals) =====================
static __device__ float g_h  [MROWS*HID];      // GCN0/1 outputs (fp32, agg input)
static __device__ float g_pre[MROWS*G4];       // LSTM input projections
static __device__ __nv_bfloat16 g_aHi[MROWS*HID], g_aLo[MROWS*HID];   // agg out planes
static __device__ __nv_bfloat16 g_hHi[MROWS*HID], g_hLo[MROWS*HID];   // GCN2 out planes
static __device__ __nv_bfloat16 g_yAHi[MROWS*OUTD], g_yALo[MROWS*OUTD];
static __device__ __nv_bfloat16 g_yBHi[MROWS*OUTD], g_yBLo[MROWS*OUTD];
static __device__ __nv_bfloat16 g_wHi[WTOT], g_wLo[WTOT];
static __device__ float g_biasc[3*G4];
static __device__ float g_dis[NN];
static __device__ int   g_cnt[NN];
static __device__ int   g_rowptr[NN+1];
static __device__ int   g_cursor[NN];
static __device__ int   g_csr_src[EE];
static __device__ float g_csr_coef[EE];

// ===================== helpers =====================
__device__ __forceinline__ uint32_t smem_u32(const void* p) {
    uint32_t a;
    asm("{ .reg .u64 t; cvta.to.shared.u64 t, %1; cvt.u32.u64 %0, t; }" : "=r"(a) : "l"(p));
    return a;
}
__device__ __forceinline__ void cp16(uint32_t s, const void* g) {
    asm volatile("cp.async.cg.shared.global [%0], [%1], 16;" :: "r"(s), "l"(g));
}
__device__ __forceinline__ void cp_commit_wait() {
    asm volatile("cp.async.commit_group;");
    asm volatile("cp.async.wait_group 0;");
}
__device__ __forceinline__ void ldsm_x4(uint32_t* r, uint32_t addr) {
    asm volatile("ldmatrix.sync.aligned.m8n8.x4.shared.b16 {%0,%1,%2,%3}, [%4];"
                 : "=r"(r[0]), "=r"(r[1]), "=r"(r[2]), "=r"(r[3]) : "r"(addr));
}
__device__ __forceinline__ void mma16816(float* d, const uint32_t* a, const uint32_t* b) {
    asm volatile(
        "mma.sync.aligned.m16n8k16.row.col.f32.bf16.bf16.f32 "
        "{%0,%1,%2,%3}, {%4,%5,%6,%7}, {%8,%9}, {%0,%1,%2,%3};"
        : "+f"(d[0]), "+f"(d[1]), "+f"(d[2]), "+f"(d[3])
        : "r"(a[0]), "r"(a[1]), "r"(a[2]), "r"(a[3]), "r"(b[0]), "r"(b[1]));
}
__device__ __forceinline__ uint32_t pack_hi2(float x, float y) {
    __nv_bfloat162 h = __halves2bfloat162(__float2bfloat16(x), __float2bfloat16(y));
    return *(uint32_t*)&h;
}
__device__ __forceinline__ uint32_t pack_lo2(float x, float y) {
    float hx = __bfloat162float(__float2bfloat16(x));
    float hy = __bfloat162float(__float2bfloat16(y));
    __nv_bfloat162 l = __halves2bfloat162(__float2bfloat16(x - hx), __float2bfloat16(y - hy));
    return *(uint32_t*)&l;
}
__device__ __forceinline__ float sigmoidf_(float x) {
    return 1.0f / (1.0f + __expf(-x));
}
__device__ __forceinline__ float tanhf_(float x) {
    return 1.0f - 2.0f / (__expf(2.0f * x) + 1.0f);
}

// ===================== setup kernels =====================
__global__ void k_zero_cnt() {
    int i = blockIdx.x * blockDim.x + threadIdx.x;
    if (i < NN) g_cnt[i] = 0;
}
__global__ void k_hist(const int* __restrict__ dst) {
    int e = blockIdx.x * blockDim.x + threadIdx.x;
    if (e < EE) atomicAdd(&g_cnt[dst[e]], 1);
}
// one block, 1024 threads: dis + exclusive scan + cursor copy
__global__ void k_scanfused() {
    const int TPB = 1024, PER = 10;
    __shared__ int sh[TPB];
    int tid = threadIdx.x;
    for (int i = tid; i < NN; i += TPB) g_dis[i] = rsqrtf((float)g_cnt[i] + 1.0f);
    int base = tid * PER;
    int loc[PER];
    int s = 0;
#pragma unroll
    for (int i = 0; i < PER; i++) {
        int idx = base + i;
        int v = (idx < NN) ? g_cnt[idx] : 0;
        loc[i] = s; s += v;
    }
    sh[tid] = s; __syncthreads();
    for (int off = 1; off < TPB; off <<= 1) {
        int v = (tid >= off) ? sh[tid - off] : 0;
        __syncthreads();
        sh[tid] += v;
        __syncthreads();
    }
    int excl = (tid == 0) ? 0 : sh[tid - 1];
#pragma unroll
    for (int i = 0; i < PER; i++) {
        int idx = base + i;
        if (idx <= NN) g_rowptr[idx] = excl + loc[i];
    }
    __syncthreads();
    for (int i = tid; i < NN; i += TPB) g_cursor[i] = g_rowptr[i];
}

// fill CSR + weight hi/lo prep + bias sums, fused into one grid
#define FILL_BLOCKS ((EE + 255) / 256)                  // 782
#define PREP_BLOCKS ((PREP_ELEMS + 255) / 256)          // 403
__global__ void k_fillprep(const int* __restrict__ src, const int* __restrict__ dst,
                           const float* __restrict__ wg0, const float* __restrict__ wg1,
                           const float* __restrict__ wg2,
                           const float* __restrict__ wih0, const float* __restrict__ wih1,
                           const float* __restrict__ wih2,
                           const float* __restrict__ bih0, const float* __restrict__ bhh0,
                           const float* __restrict__ bih1, const float* __restrict__ bhh1,
                           const float* __restrict__ bih2, const float* __restrict__ bhh2) {
    int b = blockIdx.x;
    int tid = threadIdx.x;
    if (b < FILL_BLOCKS) {
        int e = b * 256 + tid;
        if (e < EE) {
            int s = src[e], d = dst[e];
            int p = atomicAdd(&g_cursor[d], 1);
            g_csr_src[p]  = s;
            g_csr_coef[p] = g_dis[s] * g_dis[d];
        }
        return;
    }
    int idx = (b - FILL_BLOCKS) * 256 + tid;
    if (idx >= PREP_ELEMS) return;
    if (idx < WTOT) {
        float v;
        if (idx < WO1)       { int r = idx - WO0; v = wg0[(r & 31)  * HID + (r >> 5)]; }
        else if (idx < WO2)  { int r = idx - WO1; v = wg1[(r & 127) * HID + (r >> 7)]; }
        else if (idx < WO3)  { int r = idx - WO2; v = wg2[(r & 127) * HID + (r >> 7)]; }
        else if (idx < WO4)  { v = wih0[idx - WO3]; }
        else if (idx < WO5)  { v = wih1[idx - WO4]; }
        else                 { v = wih2[idx - WO5]; }
        __nv_bfloat16 h = __float2bfloat16(v);
        g_wHi[idx] = h;
        g_wLo[idx] = __float2bfloat16(v - __bfloat162float(h));
    } else {
        int r = idx - WTOT;           // 0..767
        int l = r >> 8, i = r & 255;
        const float* a = (l == 0) ? bih0 : (l == 1) ? bih1 : bih2;
        const float* c = (l == 0) ? bhh0 : (l == 1) ? bhh1 : bhh2;
        g_biasc[r] = a[i] + c[i];
    }
}

// ===================== GCN aggregation (emits bf16 hi/lo planes) =============
template <int F>
__global__ void k_agg(const float* __restrict__ in,
                      __nv_bfloat16* __restrict__ oHi, __nv_bfloat16* __restrict__ oLo) {
    int n = blockIdx.x;
    int t = threadIdx.x >> 5;
    int lane = threadIdx.x & 31;
    int p0 = g_rowptr[n], p1 = g_rowptr[n + 1];
    float d = g_dis[n];
    float sw = d * d;
    size_t m = (size_t)t * NN + n;
    if (F == 128) {
        int c0 = lane * 4;
        float4 acc = make_float4(0.f, 0.f, 0.f, 0.f);
        for (int p = p0; p < p1; p++) {
            int s = g_csr_src[p];
            float cf = g_csr_coef[p];
            float4 v = *(const float4*)(in + ((size_t)t * NN + s) * F + c0);
            acc.x += v.x * cf; acc.y += v.y * cf;
            acc.z += v.z * cf; acc.w += v.w * cf;
        }
        float4 hv = *(const float4*)(in + m * F + c0);
        float o0 = acc.x + hv.x * sw, o1 = acc.y + hv.y * sw;
        float o2 = acc.z + hv.z * sw, o3 = acc.w + hv.w * sw;
        uint2 hi = make_uint2(pack_hi2(o0, o1), pack_hi2(o2, o3));
        uint2 lo = make_uint2(pack_lo2(o0, o1), pack_lo2(o2, o3));
        *(uint2*)(oHi + m * F + c0) = hi;
        *(uint2*)(oLo + m * F + c0) = lo;
    } else {  // F == 32
        float acc = 0.0f;
        for (int p = p0; p < p1; p++) {
            int s = g_csr_src[p];
            acc += in[((size_t)t * NN + s) * F + lane] * g_csr_coef[p];
        }
        float r = acc + in[m * F + lane] * sw;
        __nv_bfloat16 h = __float2bfloat16(r);
        oHi[m * F + lane] = h;
        oLo[m * F + lane] = __float2bfloat16(r - __bfloat162float(h));
    }
}

// ===================== mma.sync bf16x3 GEMM =================================
// C = A @ W^T, A given as bf16 hi/lo planes [M][K], W as bf16 hi/lo planes
// [Nout][K]. CTA tile 128x128, 256 threads (2(M)x4(N) warps), warp tile 64x32.
// mode: 0 = +bias ; 1 = relu(.+bias) ; 2 = bn(relu(.+bias))
// output: fp32 (outF) and/or bf16 hi/lo planes (outHi/outLo)
template <int K>
__global__ void __launch_bounds__(256)
k_gemm_mma(const __nv_bfloat16* __restrict__ Ahi, const __nv_bfloat16* __restrict__ Alo,
           const __nv_bfloat16* __restrict__ Whi, const __nv_bfloat16* __restrict__ Wlo,
           const float* __restrict__ bias,
           const float* __restrict__ bng, const float* __restrict__ bnb,
           const float* __restrict__ bnm, const float* __restrict__ bnv,
           int mode, int Nout, float* __restrict__ outF,
           __nv_bfloat16* __restrict__ outHi, __nv_bfloat16* __restrict__ outLo) {
    constexpr int P  = K + 8;
    constexpr int P2 = P * 2;       // bytes per smem row
    constexpr int S  = 128 * P2;    // one tile
    constexpr int CH = K / 8;       // 16B chunks per row
    extern __shared__ char sm[];
    uint32_t sA = smem_u32(sm);

    int tid = threadIdx.x, wid = tid >> 5, lane = tid & 31;
    int wm = wid & 1, wn = wid >> 1;
    int mBase = blockIdx.x * 128;
    int jBase = blockIdx.y * 128;

    // ---- stage via cp.async: 4 planes, raw bf16 copies ----
    for (int idx = tid; idx < 128 * CH; idx += 256) {
        int row = idx / CH, c = idx % CH;
        uint32_t d = sA + row * P2 + c * 16;
        const __nv_bfloat16* ga = Ahi + (size_t)(mBase + row) * K + c * 8;
        const __nv_bfloat16* gl = Alo + (size_t)(mBase + row) * K + c * 8;
        const __nv_bfloat16* gw = Whi + (size_t)(jBase + row) * K + c * 8;
        const __nv_bfloat16* gv = Wlo + (size_t)(jBase + row) * K + c * 8;
        cp16(d,         ga);
        cp16(d + S,     gl);
        cp16(d + 2 * S, gw);
        cp16(d + 3 * S, gv);
    }
    cp_commit_wait();
    __syncthreads();

    // ---- mainloop ----
    float acc[4][4][4];
#pragma unroll
    for (int i = 0; i < 4; i++)
#pragma unroll
        for (int j = 0; j < 4; j++)
#pragma unroll
            for (int r = 0; r < 4; r++) acc[i][j][r] = 0.0f;

    uint32_t aOff = (uint32_t)((wm * 64 + (lane & 15)) * P2 + (lane >> 4) * 16);
    uint32_t bOff = (uint32_t)((wn * 32 + (lane & 7) + ((lane >> 4) << 3)) * P2 +
                               ((lane >> 3) & 1) * 16);
    uint32_t aHiB = sA + aOff;
    uint32_t aLoB = sA + S + aOff;
    uint32_t bHiB = sA + 2 * S + bOff;
    uint32_t bLoB = sA + 3 * S + bOff;

#pragma unroll
    for (int ks = 0; ks < K / 16; ks++) {
        uint32_t ka = ks * 32;
        uint32_t ah[4][4], al[4][4], bh[2][4], bl[2][4];
#pragma unroll
        for (int i = 0; i < 4; i++) {
            ldsm_x4(ah[i], aHiB + i * (16 * P2) + ka);
            ldsm_x4(al[i], aLoB + i * (16 * P2) + ka);
        }
#pragma unroll
        for (int j2 = 0; j2 < 2; j2++) {
            ldsm_x4(bh[j2], bHiB + j2 * (16 * P2) + ka);
            ldsm_x4(bl[j2], bLoB + j2 * (16 * P2) + ka);
        }
#pragma unroll
        for (int i = 0; i < 4; i++)
#pragma unroll
            for (int j = 0; j < 4; j++)
                mma16816(acc[i][j], ah[i], &bh[j >> 1][(j & 1) * 2]);
#pragma unroll
        for (int i = 0; i < 4; i++)
#pragma unroll
            for (int j = 0; j < 4; j++)
                mma16816(acc[i][j], ah[i], &bl[j >> 1][(j & 1) * 2]);
#pragma unroll
        for (int i = 0; i < 4; i++)
#pragma unroll
            for (int j = 0; j < 4; j++)
                mma16816(acc[i][j], al[i], &bh[j >> 1][(j & 1) * 2]);
    }

    // ---- epilogue ----
    float pb[4][2], psc[4][2], pmn[4][2], pbb[4][2];
#pragma unroll
    for (int j = 0; j < 4; j++) {
        int c = jBase + wn * 32 + j * 8 + (lane & 3) * 2;
#pragma unroll
        for (int q = 0; q < 2; q++) {
            pb[j][q] = bias ? bias[c + q] : 0.0f;
            if (mode == 2) {
                psc[j][q] = bng[c + q] * rsqrtf(bnv[c + q] + EPSBN);
                pmn[j][q] = bnm[c + q];
                pbb[j][q] = bnb[c + q];
            }
        }
    }
#pragma unroll
    for (int i = 0; i < 4; i++) {
        int r0 = mBase + wm * 64 + i * 16 + (lane >> 2);
#pragma unroll
        for (int j = 0; j < 4; j++) {
            int c = jBase + wn * 32 + j * 8 + (lane & 3) * 2;
            float v[4];
#pragma unroll
            for (int r = 0; r < 4; r++) {
                float x = acc[i][j][r] + pb[j][r & 1];
                if (mode >= 1) x = fmaxf(x, 0.0f);
                if (mode == 2) x = (x - pmn[j][r & 1]) * psc[j][r & 1] + pbb[j][r & 1];
                v[r] = x;
            }
            if (outF) {
                *(float2*)(outF + (size_t)r0 * Nout + c)       = make_float2(v[0], v[1]);
                *(float2*)(outF + (size_t)(r0 + 8) * Nout + c) = make_float2(v[2], v[3]);
            }
            if (outHi) {
                *(uint32_t*)(outHi + (size_t)r0 * Nout + c)       = pack_hi2(v[0], v[1]);
                *(uint32_t*)(outHi + (size_t)(r0 + 8) * Nout + c) = pack_hi2(v[2], v[3]);
                *(uint32_t*)(outLo + (size_t)r0 * Nout + c)       = pack_lo2(v[0], v[1]);
                *(uint32_t*)(outLo + (size_t)(r0 + 8) * Nout + c) = pack_lo2(v[2], v[3]);
            }
        }
    }
}

// ===================== LSTM recurrence (8 nodes / warp) ======================
#define LSTM_SMEM ((64*257 + 64*64) * 4)

__global__ void k_lstm(const float* __restrict__ pre, const float* __restrict__ whh,
                       __nv_bfloat16* __restrict__ yHi, __nv_bfloat16* __restrict__ yLo,
                       float* __restrict__ outFinal) {
    extern __shared__ float smf[];
    float* ws = smf;               // [64][257] transposed whh (padded)
    float* hs = smf + 64 * 257;    // [64 nodes][64]

    int tid  = threadIdx.x;
    int warp = tid >> 5, lane = tid & 31;
    int nodeBase = blockIdx.x * 64 + warp * 8;

    for (int idx = tid; idx < G4 * OUTD; idx += 256) {
        int j = idx >> 6, k = idx & 63;
        ws[k * 257 + j] = whh[idx];
    }
#pragma unroll
    for (int q = 0; q < 8; q++) {
        hs[(warp * 8 + q) * 64 + lane]      = 0.0f;
        hs[(warp * 8 + q) * 64 + lane + 32] = 0.0f;
    }
    float c[8][2];
#pragma unroll
    for (int q = 0; q < 8; q++) { c[q][0] = 0.0f; c[q][1] = 0.0f; }
    __syncthreads();

    for (int t = 0; t < T_STEPS; t++) {
        float g[8][8];
#pragma unroll
        for (int q = 0; q < 8; q++) {
            int n = nodeBase + q;
            if (n < NN) {
                const float* pb = pre + ((size_t)t * NN + n) * G4;
#pragma unroll
                for (int i = 0; i < 8; i++) g[q][i] = pb[i * 32 + lane];
            } else {
#pragma unroll
                for (int i = 0; i < 8; i++) g[q][i] = 0.0f;
            }
        }
#pragma unroll 4
        for (int k = 0; k < 64; k++) {
            float w[8];
#pragma unroll
            for (int i = 0; i < 8; i++) w[i] = ws[k * 257 + i * 32 + lane];
#pragma unroll
            for (int q = 0; q < 8; q++) {
                float hk = hs[(warp * 8 + q) * 64 + k];
#pragma unroll
                for (int i = 0; i < 8; i++) g[q][i] += hk * w[i];
            }
        }
        __syncwarp();
#pragma unroll
        for (int q = 0; q < 8; q++) {
            int n = nodeBase + q;
#pragma unroll
            for (int h2 = 0; h2 < 2; h2++) {
                float ig = sigmoidf_(g[q][0 + h2]);
                float fg = sigmoidf_(g[q][2 + h2]);
                float gg = tanhf_(g[q][4 + h2]);
                float og = sigmoidf_(g[q][6 + h2]);
                float cn = fg * c[q][h2] + ig * gg;
                c[q][h2] = cn;
                float hn = og * tanhf_(cn);
                int u = lane + 32 * h2;
                hs[(warp * 8 + q) * 64 + u] = hn;
                if (n < NN) {
                    if (yHi) {
                        size_t o = ((size_t)t * NN + n) * OUTD + u;
                        __nv_bfloat16 hh = __float2bfloat16(hn);
                        yHi[o] = hh;
                        yLo[o] = __float2bfloat16(hn - __bfloat162float(hh));
                    }
                    if (outFinal && t == T_STEPS - 1)
                        outFinal[(size_t)n * OUTD + u] = hn;
                }
            }
        }
        __syncwarp();
    }
}

// ===================== host =====================
extern "C" void kernel_launch(void* const* d_in, const int* in_sizes, int n_in,
                              void* d_out, int out_size) {
    const float* x   = (const float*)d_in[0];
    const int*   ei  = (const int*)d_in[1];
    const int*   src = ei;
    const int*   dst = ei + EE;
    const float* wg[3] = {(const float*)d_in[2], (const float*)d_in[4], (const float*)d_in[6]};
    const float* bg[3] = {(const float*)d_in[3], (const float*)d_in[5], (const float*)d_in[7]};
    const float* bnG[2] = {(const float*)d_in[8],  (const float*)d_in[12]};
    const float* bnB[2] = {(const float*)d_in[9],  (const float*)d_in[13]};
    const float* bnM[2] = {(const float*)d_in[10], (const float*)d_in[14]};
    const float* bnV[2] = {(const float*)d_in[11], (const float*)d_in[15]};
    const float* wih[3] = {(const float*)d_in[16], (const float*)d_in[20], (const float*)d_in[24]};
    const float* whh[3] = {(const float*)d_in[17], (const float*)d_in[21], (const float*)d_in[25]};
    const float* bih[3] = {(const float*)d_in[18], (const float*)d_in[22], (const float*)d_in[26]};
    const float* bhh[3] = {(const float*)d_in[19], (const float*)d_in[23], (const float*)d_in[27]};
    float* out = (float*)d_out;

    float *p_h, *p_pre, *p_bias;
    __nv_bfloat16 *p_aHi, *p_aLo, *p_hHi, *p_hLo, *p_yAHi, *p_yALo, *p_yBHi, *p_yBLo, *p_wHi, *p_wLo;
    cudaGetSymbolAddress((void**)&p_h,    g_h);
    cudaGetSymbolAddress((void**)&p_pre,  g_pre);
    cudaGetSymbolAddress((void**)&p_bias, g_biasc);
    cudaGetSymbolAddress((void**)&p_aHi,  g_aHi);
    cudaGetSymbolAddress((void**)&p_aLo,  g_aLo);
    cudaGetSymbolAddress((void**)&p_hHi,  g_hHi);
    cudaGetSymbolAddress((void**)&p_hLo,  g_hLo);
    cudaGetSymbolAddress((void**)&p_yAHi, g_yAHi);
    cudaGetSymbolAddress((void**)&p_yALo, g_yALo);
    cudaGetSymbolAddress((void**)&p_yBHi, g_yBHi);
    cudaGetSymbolAddress((void**)&p_yBLo, g_yBLo);
    cudaGetSymbolAddress((void**)&p_wHi,  g_wHi);
    cudaGetSymbolAddress((void**)&p_wLo,  g_wLo);

    const int SM32  = 4 * 128 * (32  + 8) * 2;   //  40960
    const int SM64  = 4 * 128 * (64  + 8) * 2;   //  73728
    const int SM128 = 4 * 128 * (128 + 8) * 2;   // 139264
    cudaFuncSetAttribute(k_gemm_mma<32>,  cudaFuncAttributeMaxDynamicSharedMemorySize, SM32);
    cudaFuncSetAttribute(k_gemm_mma<64>,  cudaFuncAttributeMaxDynamicSharedMemorySize, SM64);
    cudaFuncSetAttribute(k_gemm_mma<128>, cudaFuncAttributeMaxDynamicSharedMemorySize, SM128);
    cudaFuncSetAttribute(k_lstm, cudaFuncAttributeMaxDynamicSharedMemorySize, LSTM_SMEM);

    // ---- setup (4 launches) ----
    k_zero_cnt<<<(NN + 255) / 256, 256>>>();
    k_hist<<<(EE + 255) / 256, 256>>>(dst);
    k_scanfused<<<1, 1024>>>();
    k_fillprep<<<FILL_BLOCKS + PREP_BLOCKS, 256>>>(
        src, dst, wg[0], wg[1], wg[2], wih[0], wih[1], wih[2],
        bih[0], bhh[0], bih[1], bhh[1], bih[2], bhh[2]);

    const int MT = MROWS / 128;  // 625 M tiles

    // ---- GCN 0: agg(x) [F=32] -> bn(relu(.@W0 + b0)) ----
    k_agg<32><<<NN, 256>>>(x, p_aHi, p_aLo);
    k_gemm_mma<32><<<dim3(MT, 1), 256, SM32>>>(
        p_aHi, p_aLo, p_wHi + WO0, p_wLo + WO0, bg[0],
        bnG[0], bnB[0], bnM[0], bnV[0], 2, HID, p_h, nullptr, nullptr);
    // ---- GCN 1 ----
    k_agg<128><<<NN, 256>>>(p_h, p_aHi, p_aLo);
    k_gemm_mma<128><<<dim3(MT, 1), 256, SM128>>>(
        p_aHi, p_aLo, p_wHi + WO1, p_wLo + WO1, bg[1],
        bnG[1], bnB[1], bnM[1], bnV[1], 2, HID, p_h, nullptr, nullptr);
    // ---- GCN 2 (relu only, emit bf16 planes) ----
    k_agg<128><<<NN, 256>>>(p_h, p_aHi, p_aLo);
    k_gemm_mma<128><<<dim3(MT, 1), 256, SM128>>>(
        p_aHi, p_aLo, p_wHi + WO2, p_wLo + WO2, bg[2],
        nullptr, nullptr, nullptr, nullptr, 1, HID, nullptr, p_hHi, p_hLo);

    int lstmBlocks = (NN + 63) / 64;  // 157
    // ---- LSTM layer 0 ----
    k_gemm_mma<128><<<dim3(MT, 2), 256, SM128>>>(
        p_hHi, p_hLo, p_wHi + WO3, p_wLo + WO3, p_bias + 0 * G4,
        nullptr, nullptr, nullptr, nullptr, 0, G4, p_pre, nullptr, nullptr);
    k_lstm<<<lstmBlocks, 256, LSTM_SMEM>>>(p_pre, whh[0], p_yAHi, p_yALo, nullptr);
    // ---- LSTM layer 1 ----
    k_gemm_mma<64><<<dim3(MT, 2), 256, SM64>>>(
        p_yAHi, p_yALo, p_wHi + WO4, p_wLo + WO4, p_bias + 1 * G4,
        nullptr, nullptr, nullptr, nullptr, 0, G4, p_pre, nullptr, nullptr);
    k_lstm<<<lstmBlocks, 256, LSTM_SMEM>>>(p_pre, whh[1], p_yBHi, p_yBLo, nullptr);
    // ---- LSTM layer 2 ----
    k_gemm_mma<64><<<dim3(MT, 2), 256, SM64>>>(
        p_yBHi, p_yBLo, p_wHi + WO5, p_wLo + WO5, p_bias + 2 * G4,
        nullptr, nullptr, nullptr, nullptr, 0, G4, p_pre, nullptr, nullptr);
    k_lstm<<<lstmBlocks, 256, LSTM_SMEM>>>(p_pre, whh[2], nullptr, nullptr, out);
}

// round 5
// speedup vs baseline: 1.4104x; 1.4104x over previous
#include <cuda_runtime.h>
#include <cuda_bf16.h>
#include <math.h>
#include <stdint.h>

#define T_STEPS 8
#define NN      10000
#define EE      200000
#define FIN     32
#define HID     128
#define OUTD    64
#define G4      256            // 4*OUT
#define MROWS   (T_STEPS*NN)   // 80000
#define EPSBN   1e-5f

// weight-plane offsets ([n][k] bf16 layout, packed)
#define WO0 0            // wg0^T   128x32
#define WO1 4096         // wg1^T   128x128
#define WO2 20480        // wg2^T   128x128
#define WO3 36864        // w_ih0   256x128
#define WO4 69632        // w_ih1   256x64
#define WO5 86016        // w_ih2   256x64
#define WTOT 102400
#define PREP_ELEMS (WTOT + 768)

// ===================== scratch (device globals) =====================
static __device__ float g_h  [MROWS*HID];      // GCN0/1 outputs (fp32, agg input)
static __device__ float g_pre[MROWS*G4];       // LSTM input projections
static __device__ __nv_bfloat16 g_aHi[MROWS*HID], g_aLo[MROWS*HID];   // agg out planes
static __device__ __nv_bfloat16 g_hHi[MROWS*HID], g_hLo[MROWS*HID];   // GCN2 out planes
static __device__ __nv_bfloat16 g_yAHi[MROWS*OUTD], g_yALo[MROWS*OUTD];
static __device__ __nv_bfloat16 g_yBHi[MROWS*OUTD], g_yBLo[MROWS*OUTD];
static __device__ __nv_bfloat16 g_wHi[WTOT], g_wLo[WTOT];
static __device__ float g_biasc[3*G4];
static __device__ float g_dis[NN];
static __device__ int   g_cnt[NN];
static __device__ int   g_rowptr[NN+1];
static __device__ int   g_cursor[NN];
static __device__ int   g_csr_src[EE];
static __device__ float g_csr_coef[EE];

// ===================== helpers =====================
__device__ __forceinline__ uint32_t smem_u32(const void* p) {
    uint32_t a;
    asm("{ .reg .u64 t; cvta.to.shared.u64 t, %1; cvt.u32.u64 %0, t; }" : "=r"(a) : "l"(p));
    return a;
}
__device__ __forceinline__ void cp16(uint32_t s, const void* g) {
    asm volatile("cp.async.cg.shared.global [%0], [%1], 16;" :: "r"(s), "l"(g));
}
__device__ __forceinline__ void cp_commit_wait() {
    asm volatile("cp.async.commit_group;");
    asm volatile("cp.async.wait_group 0;");
}
__device__ __forceinline__ void ldsm_x4(uint32_t* r, uint32_t addr) {
    asm volatile("ldmatrix.sync.aligned.m8n8.x4.shared.b16 {%0,%1,%2,%3}, [%4];"
                 : "=r"(r[0]), "=r"(r[1]), "=r"(r[2]), "=r"(r[3]) : "r"(addr));
}
__device__ __forceinline__ void mma16816(float* d, const uint32_t* a, const uint32_t* b) {
    asm volatile(
        "mma.sync.aligned.m16n8k16.row.col.f32.bf16.bf16.f32 "
        "{%0,%1,%2,%3}, {%4,%5,%6,%7}, {%8,%9}, {%0,%1,%2,%3};"
        : "+f"(d[0]), "+f"(d[1]), "+f"(d[2]), "+f"(d[3])
        : "r"(a[0]), "r"(a[1]), "r"(a[2]), "r"(a[3]), "r"(b[0]), "r"(b[1]));
}
__device__ __forceinline__ uint32_t pack_hi2(float x, float y) {
    __nv_bfloat162 h = __halves2bfloat162(__float2bfloat16(x), __float2bfloat16(y));
    return *(uint32_t*)&h;
}
__device__ __forceinline__ uint32_t pack_lo2(float x, float y) {
    float hx = __bfloat162float(__float2bfloat16(x));
    float hy = __bfloat162float(__float2bfloat16(y));
    __nv_bfloat162 l = __halves2bfloat162(__float2bfloat16(x - hx), __float2bfloat16(y - hy));
    return *(uint32_t*)&l;
}
__device__ __forceinline__ float sigmoidf_(float x) {
    return 1.0f / (1.0f + __expf(-x));
}
__device__ __forceinline__ float tanhf_(float x) {
    return 1.0f - 2.0f / (__expf(2.0f * x) + 1.0f);
}

// ===================== setup kernels =====================
__global__ void k_zero_cnt() {
    int i = blockIdx.x * blockDim.x + threadIdx.x;
    if (i < NN) g_cnt[i] = 0;
}
__global__ void k_hist(const int* __restrict__ dst) {
    int e = blockIdx.x * blockDim.x + threadIdx.x;
    if (e < EE) atomicAdd(&g_cnt[dst[e]], 1);
}
__global__ void k_scanfused() {
    const int TPB = 1024, PER = 10;
    __shared__ int sh[TPB];
    int tid = threadIdx.x;
    for (int i = tid; i < NN; i += TPB) g_dis[i] = rsqrtf((float)g_cnt[i] + 1.0f);
    int base = tid * PER;
    int loc[PER];
    int s = 0;
#pragma unroll
    for (int i = 0; i < PER; i++) {
        int idx = base + i;
        int v = (idx < NN) ? g_cnt[idx] : 0;
        loc[i] = s; s += v;
    }
    sh[tid] = s; __syncthreads();
    for (int off = 1; off < TPB; off <<= 1) {
        int v = (tid >= off) ? sh[tid - off] : 0;
        __syncthreads();
        sh[tid] += v;
        __syncthreads();
    }
    int excl = (tid == 0) ? 0 : sh[tid - 1];
#pragma unroll
    for (int i = 0; i < PER; i++) {
        int idx = base + i;
        if (idx <= NN) g_rowptr[idx] = excl + loc[i];
    }
    __syncthreads();
    for (int i = tid; i < NN; i += TPB) g_cursor[i] = g_rowptr[i];
}

#define FILL_BLOCKS ((EE + 255) / 256)
#define PREP_BLOCKS ((PREP_ELEMS + 255) / 256)
__global__ void k_fillprep(const int* __restrict__ src, const int* __restrict__ dst,
                           const float* __restrict__ wg0, const float* __restrict__ wg1,
                           const float* __restrict__ wg2,
                           const float* __restrict__ wih0, const float* __restrict__ wih1,
                           const float* __restrict__ wih2,
                           const float* __restrict__ bih0, const float* __restrict__ bhh0,
                           const float* __restrict__ bih1, const float* __restrict__ bhh1,
                           const float* __restrict__ bih2, const float* __restrict__ bhh2) {
    int b = blockIdx.x;
    int tid = threadIdx.x;
    if (b < FILL_BLOCKS) {
        int e = b * 256 + tid;
        if (e < EE) {
            int s = src[e], d = dst[e];
            int p = atomicAdd(&g_cursor[d], 1);
            g_csr_src[p]  = s;
            g_csr_coef[p] = g_dis[s] * g_dis[d];
        }
        return;
    }
    int idx = (b - FILL_BLOCKS) * 256 + tid;
    if (idx >= PREP_ELEMS) return;
    if (idx < WTOT) {
        float v;
        if (idx < WO1)       { int r = idx - WO0; v = wg0[(r & 31)  * HID + (r >> 5)]; }
        else if (idx < WO2)  { int r = idx - WO1; v = wg1[(r & 127) * HID + (r >> 7)]; }
        else if (idx < WO3)  { int r = idx - WO2; v = wg2[(r & 127) * HID + (r >> 7)]; }
        else if (idx < WO4)  { v = wih0[idx - WO3]; }
        else if (idx < WO5)  { v = wih1[idx - WO4]; }
        else                 { v = wih2[idx - WO5]; }
        __nv_bfloat16 h = __float2bfloat16(v);
        g_wHi[idx] = h;
        g_wLo[idx] = __float2bfloat16(v - __bfloat162float(h));
    } else {
        int r = idx - WTOT;
        int l = r >> 8, i = r & 255;
        const float* a = (l == 0) ? bih0 : (l == 1) ? bih1 : bih2;
        const float* c = (l == 0) ? bhh0 : (l == 1) ? bhh1 : bhh2;
        g_biasc[r] = a[i] + c[i];
    }
}

// ===================== GCN aggregation (emits bf16 hi/lo planes) =============
template <int F>
__global__ void k_agg(const float* __restrict__ in,
                      __nv_bfloat16* __restrict__ oHi, __nv_bfloat16* __restrict__ oLo) {
    int n = blockIdx.x;
    int t = threadIdx.x >> 5;
    int lane = threadIdx.x & 31;
    int p0 = g_rowptr[n], p1 = g_rowptr[n + 1];
    float d = g_dis[n];
    float sw = d * d;
    size_t m = (size_t)t * NN + n;
    if (F == 128) {
        int c0 = lane * 4;
        float4 acc = make_float4(0.f, 0.f, 0.f, 0.f);
        for (int p = p0; p < p1; p++) {
            int s = g_csr_src[p];
            float cf = g_csr_coef[p];
            float4 v = *(const float4*)(in + ((size_t)t * NN + s) * F + c0);
            acc.x += v.x * cf; acc.y += v.y * cf;
            acc.z += v.z * cf; acc.w += v.w * cf;
        }
        float4 hv = *(const float4*)(in + m * F + c0);
        float o0 = acc.x + hv.x * sw, o1 = acc.y + hv.y * sw;
        float o2 = acc.z + hv.z * sw, o3 = acc.w + hv.w * sw;
        uint2 hi = make_uint2(pack_hi2(o0, o1), pack_hi2(o2, o3));
        uint2 lo = make_uint2(pack_lo2(o0, o1), pack_lo2(o2, o3));
        *(uint2*)(oHi + m * F + c0) = hi;
        *(uint2*)(oLo + m * F + c0) = lo;
    } else {  // F == 32
        float acc = 0.0f;
        for (int p = p0; p < p1; p++) {
            int s = g_csr_src[p];
            acc += in[((size_t)t * NN + s) * F + lane] * g_csr_coef[p];
        }
        float r = acc + in[m * F + lane] * sw;
        __nv_bfloat16 h = __float2bfloat16(r);
        oHi[m * F + lane] = h;
        oLo[m * F + lane] = __float2bfloat16(r - __bfloat162float(h));
    }
}

// ===================== mma.sync bf16x3 GEMM (K-chunked, 2 CTA/SM) ===========
// C = A @ W^T. A: bf16 hi/lo planes [M][K]; W: bf16 hi/lo planes [Nout][K].
// CTA tile 128x128, 256 threads (2(M)x4(N) warps), warp tile 64x32.
// K staged in chunks of KC=min(K,64) -> smem 4*128*(KC+8)*2 <= 73728.
// mode: 0 = +bias ; 1 = relu(.+bias) ; 2 = bn(relu(.+bias))
template <int K>
__global__ void __launch_bounds__(256, 2)
k_gemm_mma(const __nv_bfloat16* __restrict__ Ahi, const __nv_bfloat16* __restrict__ Alo,
           const __nv_bfloat16* __restrict__ Whi, const __nv_bfloat16* __restrict__ Wlo,
           const float* __restrict__ bias,
           const float* __restrict__ bng, const float* __restrict__ bnb,
           const float* __restrict__ bnm, const float* __restrict__ bnv,
           int mode, int Nout, float* __restrict__ outF,
           __nv_bfloat16* __restrict__ outHi, __nv_bfloat16* __restrict__ outLo) {
    constexpr int KC  = (K > 64) ? 64 : K;
    constexpr int NCH = K / KC;
    constexpr int P   = KC + 8;
    constexpr int P2  = P * 2;
    constexpr int S   = 128 * P2;
    constexpr int CH16 = KC / 8;
    extern __shared__ char sm[];
    uint32_t sA = smem_u32(sm);

    int tid = threadIdx.x, wid = tid >> 5, lane = tid & 31;
    int wm = wid & 1, wn = wid >> 1;
    int mBase = blockIdx.x * 128;
    int jBase = blockIdx.y * 128;

    float acc[4][4][4];
#pragma unroll
    for (int i = 0; i < 4; i++)
#pragma unroll
        for (int j = 0; j < 4; j++)
#pragma unroll
            for (int r = 0; r < 4; r++) acc[i][j][r] = 0.0f;

    uint32_t aOff = (uint32_t)((wm * 64 + (lane & 15)) * P2 + (lane >> 4) * 16);
    uint32_t bOff = (uint32_t)((wn * 32 + (lane & 7) + ((lane >> 4) << 3)) * P2 +
                               ((lane >> 3) & 1) * 16);

#pragma unroll
    for (int ch = 0; ch < NCH; ch++) {
        // ---- stage chunk: 4 planes via cp.async ----
        for (int idx = tid; idx < 128 * CH16; idx += 256) {
            int row = idx / CH16, c = idx % CH16;
            uint32_t d = sA + row * P2 + c * 16;
            size_t ga = (size_t)(mBase + row) * K + ch * KC + c * 8;
            size_t gw = (size_t)(jBase + row) * K + ch * KC + c * 8;
            cp16(d,         Ahi + ga);
            cp16(d + S,     Alo + ga);
            cp16(d + 2 * S, Whi + gw);
            cp16(d + 3 * S, Wlo + gw);
        }
        cp_commit_wait();
        __syncthreads();

        // ---- mainloop (register-pressure-aware ordering) ----
#pragma unroll
        for (int ks = 0; ks < KC / 16; ks++) {
            uint32_t ka = ks * 32;
            uint32_t bh[2][4], bl[2][4];
#pragma unroll
            for (int j2 = 0; j2 < 2; j2++) {
                ldsm_x4(bh[j2], sA + 2 * S + bOff + j2 * (16 * P2) + ka);
                ldsm_x4(bl[j2], sA + 3 * S + bOff + j2 * (16 * P2) + ka);
            }
#pragma unroll
            for (int i = 0; i < 4; i++) {
                uint32_t ah[4], al[4];
                ldsm_x4(ah, sA + aOff + i * (16 * P2) + ka);
                ldsm_x4(al, sA + S + aOff + i * (16 * P2) + ka);
#pragma unroll
                for (int j = 0; j < 4; j++) {
                    mma16816(acc[i][j], ah, &bh[j >> 1][(j & 1) * 2]);
                    mma16816(acc[i][j], ah, &bl[j >> 1][(j & 1) * 2]);
                    mma16816(acc[i][j], al, &bh[j >> 1][(j & 1) * 2]);
                }
            }
        }
        if (ch + 1 < NCH) __syncthreads();
    }

    // ---- epilogue ----
    float pb[4][2], psc[4][2], pmn[4][2], pbb[4][2];
#pragma unroll
    for (int j = 0; j < 4; j++) {
        int c = jBase + wn * 32 + j * 8 + (lane & 3) * 2;
#pragma unroll
        for (int q = 0; q < 2; q++) {
            pb[j][q] = bias ? bias[c + q] : 0.0f;
            if (mode == 2) {
                psc[j][q] = bng[c + q] * rsqrtf(bnv[c + q] + EPSBN);
                pmn[j][q] = bnm[c + q];
                pbb[j][q] = bnb[c + q];
            }
        }
    }
#pragma unroll
    for (int i = 0; i < 4; i++) {
        int r0 = mBase + wm * 64 + i * 16 + (lane >> 2);
#pragma unroll
        for (int j = 0; j < 4; j++) {
            int c = jBase + wn * 32 + j * 8 + (lane & 3) * 2;
            float v[4];
#pragma unroll
            for (int r = 0; r < 4; r++) {
                float x = acc[i][j][r] + pb[j][r & 1];
                if (mode >= 1) x = fmaxf(x, 0.0f);
                if (mode == 2) x = (x - pmn[j][r & 1]) * psc[j][r & 1] + pbb[j][r & 1];
                v[r] = x;
            }
            if (outF) {
                *(float2*)(outF + (size_t)r0 * Nout + c)       = make_float2(v[0], v[1]);
                *(float2*)(outF + (size_t)(r0 + 8) * Nout + c) = make_float2(v[2], v[3]);
            }
            if (outHi) {
                *(uint32_t*)(outHi + (size_t)r0 * Nout + c)       = pack_hi2(v[0], v[1]);
                *(uint32_t*)(outHi + (size_t)(r0 + 8) * Nout + c) = pack_hi2(v[2], v[3]);
                *(uint32_t*)(outLo + (size_t)r0 * Nout + c)       = pack_lo2(v[0], v[1]);
                *(uint32_t*)(outLo + (size_t)(r0 + 8) * Nout + c) = pack_lo2(v[2], v[3]);
            }
        }
    }
}

// ===================== LSTM recurrence (4 nodes / warp) ======================
#define LSTM_SMEM ((64*257 + 32*64) * 4)

__global__ void k_lstm(const float* __restrict__ pre, const float* __restrict__ whh,
                       __nv_bfloat16* __restrict__ yHi, __nv_bfloat16* __restrict__ yLo,
                       float* __restrict__ outFinal) {
    extern __shared__ float smf[];
    float* ws = smf;               // [64][257] transposed whh (padded)
    float* hs = smf + 64 * 257;    // [32 nodes][64]

    int tid  = threadIdx.x;
    int warp = tid >> 5, lane = tid & 31;
    int nodeBase = blockIdx.x * 32 + warp * 4;

    for (int idx = tid; idx < G4 * OUTD; idx += 256) {
        int j = idx >> 6, k = idx & 63;
        ws[k * 257 + j] = whh[idx];
    }
#pragma unroll
    for (int q = 0; q < 4; q++) {
        hs[(warp * 4 + q) * 64 + lane]      = 0.0f;
        hs[(warp * 4 + q) * 64 + lane + 32] = 0.0f;
    }
    float c[4][2];
#pragma unroll
    for (int q = 0; q < 4; q++) { c[q][0] = 0.0f; c[q][1] = 0.0f; }
    __syncthreads();

    for (int t = 0; t < T_STEPS; t++) {
        float g[4][8];
#pragma unroll
        for (int q = 0; q < 4; q++) {
            int n = nodeBase + q;
            if (n < NN) {
                const float* pb = pre + ((size_t)t * NN + n) * G4;
#pragma unroll
                for (int i = 0; i < 8; i++) g[q][i] = pb[i * 32 + lane];
            } else {
#pragma unroll
                for (int i = 0; i < 8; i++) g[q][i] = 0.0f;
            }
        }
#pragma unroll 4
        for (int k = 0; k < 64; k++) {
            float w[8];
#pragma unroll
            for (int i = 0; i < 8; i++) w[i] = ws[k * 257 + i * 32 + lane];
#pragma unroll
            for (int q = 0; q < 4; q++) {
                float hk = hs[(warp * 4 + q) * 64 + k];
#pragma unroll
                for (int i = 0; i < 8; i++) g[q][i] += hk * w[i];
            }
        }
        __syncwarp();
#pragma unroll
        for (int q = 0; q < 4; q++) {
            int n = nodeBase + q;
#pragma unroll
            for (int h2 = 0; h2 < 2; h2++) {
                float ig = sigmoidf_(g[q][0 + h2]);
                float fg = sigmoidf_(g[q][2 + h2]);
                float gg = tanhf_(g[q][4 + h2]);
                float og = sigmoidf_(g[q][6 + h2]);
                float cn = fg * c[q][h2] + ig * gg;
                c[q][h2] = cn;
                float hn = og * tanhf_(cn);
                int u = lane + 32 * h2;
                hs[(warp * 4 + q) * 64 + u] = hn;
                if (n < NN) {
                    if (yHi) {
                        size_t o = ((size_t)t * NN + n) * OUTD + u;
                        __nv_bfloat16 hh = __float2bfloat16(hn);
                        yHi[o] = hh;
                        yLo[o] = __float2bfloat16(hn - __bfloat162float(hh));
                    }
                    if (outFinal && t == T_STEPS - 1)
                        outFinal[(size_t)n * OUTD + u] = hn;
                }
            }
        }
        __syncwarp();
    }
}

// ===================== host =====================
extern "C" void kernel_launch(void* const* d_in, const int* in_sizes, int n_in,
                              void* d_out, int out_size) {
    const float* x   = (const float*)d_in[0];
    const int*   ei  = (const int*)d_in[1];
    const int*   src = ei;
    const int*   dst = ei + EE;
    const float* wg[3] = {(const float*)d_in[2], (const float*)d_in[4], (const float*)d_in[6]};
    const float* bg[3] = {(const float*)d_in[3], (const float*)d_in[5], (const float*)d_in[7]};
    const float* bnG[2] = {(const float*)d_in[8],  (const float*)d_in[12]};
    const float* bnB[2] = {(const float*)d_in[9],  (const float*)d_in[13]};
    const float* bnM[2] = {(const float*)d_in[10], (const float*)d_in[14]};
    const float* bnV[2] = {(const float*)d_in[11], (const float*)d_in[15]};
    const float* wih[3] = {(const float*)d_in[16], (const float*)d_in[20], (const float*)d_in[24]};
    const float* whh[3] = {(const float*)d_in[17], (const float*)d_in[21], (const float*)d_in[25]};
    const float* bih[3] = {(const float*)d_in[18], (const float*)d_in[22], (const float*)d_in[26]};
    const float* bhh[3] = {(const float*)d_in[19], (const float*)d_in[23], (const float*)d_in[27]};
    float* out = (float*)d_out;

    float *p_h, *p_pre, *p_bias;
    __nv_bfloat16 *p_aHi, *p_aLo, *p_hHi, *p_hLo, *p_yAHi, *p_yALo, *p_yBHi, *p_yBLo, *p_wHi, *p_wLo;
    cudaGetSymbolAddress((void**)&p_h,    g_h);
    cudaGetSymbolAddress((void**)&p_pre,  g_pre);
    cudaGetSymbolAddress((void**)&p_bias, g_biasc);
    cudaGetSymbolAddress((void**)&p_aHi,  g_aHi);
    cudaGetSymbolAddress((void**)&p_aLo,  g_aLo);
    cudaGetSymbolAddress((void**)&p_hHi,  g_hHi);
    cudaGetSymbolAddress((void**)&p_hLo,  g_hLo);
    cudaGetSymbolAddress((void**)&p_yAHi, g_yAHi);
    cudaGetSymbolAddress((void**)&p_yALo, g_yALo);
    cudaGetSymbolAddress((void**)&p_yBHi, g_yBHi);
    cudaGetSymbolAddress((void**)&p_yBLo, g_yBLo);
    cudaGetSymbolAddress((void**)&p_wHi,  g_wHi);
    cudaGetSymbolAddress((void**)&p_wLo,  g_wLo);

    const int SM32 = 4 * 128 * (32 + 8) * 2;   // 40960
    const int SM64 = 4 * 128 * (64 + 8) * 2;   // 73728 (also used for K=128 chunked)
    cudaFuncSetAttribute(k_gemm_mma<32>,  cudaFuncAttributeMaxDynamicSharedMemorySize, SM32);
    cudaFuncSetAttribute(k_gemm_mma<64>,  cudaFuncAttributeMaxDynamicSharedMemorySize, SM64);
    cudaFuncSetAttribute(k_gemm_mma<128>, cudaFuncAttributeMaxDynamicSharedMemorySize, SM64);
    cudaFuncSetAttribute(k_lstm, cudaFuncAttributeMaxDynamicSharedMemorySize, LSTM_SMEM);

    // ---- setup ----
    k_zero_cnt<<<(NN + 255) / 256, 256>>>();
    k_hist<<<(EE + 255) / 256, 256>>>(dst);
    k_scanfused<<<1, 1024>>>();
    k_fillprep<<<FILL_BLOCKS + PREP_BLOCKS, 256>>>(
        src, dst, wg[0], wg[1], wg[2], wih[0], wih[1], wih[2],
        bih[0], bhh[0], bih[1], bhh[1], bih[2], bhh[2]);

    const int MT = MROWS / 128;  // 625 M tiles

    // ---- GCN 0 ----
    k_agg<32><<<NN, 256>>>(x, p_aHi, p_aLo);
    k_gemm_mma<32><<<dim3(MT, 1), 256, SM32>>>(
        p_aHi, p_aLo, p_wHi + WO0, p_wLo + WO0, bg[0],
        bnG[0], bnB[0], bnM[0], bnV[0], 2, HID, p_h, nullptr, nullptr);
    // ---- GCN 1 ----
    k_agg<128><<<NN, 256>>>(p_h, p_aHi, p_aLo);
    k_gemm_mma<128><<<dim3(MT, 1), 256, SM64>>>(
        p_aHi, p_aLo, p_wHi + WO1, p_wLo + WO1, bg[1],
        bnG[1], bnB[1], bnM[1], bnV[1], 2, HID, p_h, nullptr, nullptr);
    // ---- GCN 2 (relu only, emit bf16 planes) ----
    k_agg<128><<<NN, 256>>>(p_h, p_aHi, p_aLo);
    k_gemm_mma<128><<<dim3(MT, 1), 256, SM64>>>(
        p_aHi, p_aLo, p_wHi + WO2, p_wLo + WO2, bg[2],
        nullptr, nullptr, nullptr, nullptr, 1, HID, nullptr, p_hHi, p_hLo);

    int lstmBlocks = (NN + 31) / 32;  // 313
    // ---- LSTM layer 0 ----
    k_gemm_mma<128><<<dim3(MT, 2), 256, SM64>>>(
        p_hHi, p_hLo, p_wHi + WO3, p_wLo + WO3, p_bias + 0 * G4,
        nullptr, nullptr, nullptr, nullptr, 0, G4, p_pre, nullptr, nullptr);
    k_lstm<<<lstmBlocks, 256, LSTM_SMEM>>>(p_pre, whh[0], p_yAHi, p_yALo, nullptr);
    // ---- LSTM layer 1 ----
    k_gemm_mma<64><<<dim3(MT, 2), 256, SM64>>>(
        p_yAHi, p_yALo, p_wHi + WO4, p_wLo + WO4, p_bias + 1 * G4,
        nullptr, nullptr, nullptr, nullptr, 0, G4, p_pre, nullptr, nullptr);
    k_lstm<<<lstmBlocks, 256, LSTM_SMEM>>>(p_pre, whh[1], p_yBHi, p_yBLo, nullptr);
    // ---- LSTM layer 2 ----
    k_gemm_mma<64><<<dim3(MT, 2), 256, SM64>>>(
        p_yBHi, p_yBLo, p_wHi + WO5, p_wLo + WO5, p_bias + 2 * G4,
        nullptr, nullptr, nullptr, nullptr, 0, G4, p_pre, nullptr, nullptr);
    k_lstm<<<lstmBlocks, 256, LSTM_SMEM>>>(p_pre, whh[2], nullptr, nullptr, out);
}